// round 7
// baseline (speedup 1.0000x reference)
#include <cuda_runtime.h>
#include <cuda_bf16.h>
#include <cstdint>

#define BATCH 2048
#define RPB   128      // rows per MLP CTA
#define NCTA  16
#define NTHR  256      // 8 warps x 16 rows
#define XCOLS 39
#define HID   128

// ---- MLP kernel smem byte offsets ----
#define EA_PITCH  176            // 88 bf16 per row (80 + 8 pad)
#define W_PITCH   272            // 136 bf16 per row (128 + 8 pad)
#define OFF_EA_HI 0              // emb A hi [128][88] bf16   22528
#define OFF_EA_LO 22528          //                            22528
#define OFF_W0_HI 45056          // W buf0 hi [128][136] bf16 34816
#define OFF_W0_LO 79872
#define OFF_W1_HI 114688
#define OFF_W1_LO 149504
#define OFF_WC2   184320         // wc2bar [128][8] f32        4096
#define OFF_CBAR  188416         // cbar [128][8] f32          4096
#define OFF_BF1   192512         // biases f32 [128] each
#define OFF_BF2   193024
#define OFF_BC1   193536
#define OFF_BB1   194048
#define OFF_BC2   194560         // bc2bar[6] + bb2 at [6]       32
#define OFF_WB2   194592         // Wb2 [128] f32               512
#define MLP_SMEM  195104

__device__ float g_scratch[BATCH * 16];   // [row][m0..m2: B0..B3][m3: sbase,-,-,-]

// ---------------- PTX wrappers ----------------
__device__ __forceinline__ void ldm4(uint32_t r[4], uint32_t a) {
    asm volatile("ldmatrix.sync.aligned.m8n8.x4.shared.b16 {%0,%1,%2,%3}, [%4];"
                 : "=r"(r[0]), "=r"(r[1]), "=r"(r[2]), "=r"(r[3]) : "r"(a));
}
__device__ __forceinline__ void ldm4t(uint32_t r[4], uint32_t a) {
    asm volatile("ldmatrix.sync.aligned.m8n8.x4.trans.shared.b16 {%0,%1,%2,%3}, [%4];"
                 : "=r"(r[0]), "=r"(r[1]), "=r"(r[2]), "=r"(r[3]) : "r"(a));
}
__device__ __forceinline__ void mma_bf16(float d[4], const uint32_t a[4],
                                         uint32_t b0, uint32_t b1) {
    asm("mma.sync.aligned.m16n8k16.row.col.f32.bf16.bf16.f32 "
        "{%0,%1,%2,%3}, {%4,%5,%6,%7}, {%8,%9}, {%0,%1,%2,%3};"
        : "+f"(d[0]), "+f"(d[1]), "+f"(d[2]), "+f"(d[3])
        : "r"(a[0]), "r"(a[1]), "r"(a[2]), "r"(a[3]), "r"(b0), "r"(b1));
}
// fp32 pair -> bf16x2 hi + bf16x2 lo (v0 in low half)
__device__ __forceinline__ void split2(float v0, float v1, uint32_t& hi, uint32_t& lo) {
    __nv_bfloat162 h = __floats2bfloat162_rn(v0, v1);
    float f0 = __bfloat162float(h.x), f1 = __bfloat162float(h.y);
    __nv_bfloat162 g = __floats2bfloat162_rn(v0 - f0, v1 - f1);
    hi = *reinterpret_cast<uint32_t*>(&h);
    lo = *reinterpret_cast<uint32_t*>(&g);
}

// stage fp32 W[K][128] -> bf16 hi/lo smem tiles [K][136]
__device__ __forceinline__ void stageW(const float* __restrict__ W, int K,
                                       char* smem, int offH, int offL, int tid)
{
    int tot = K * 32;
    for (int i = tid; i < tot; i += NTHR) {
        int k = i >> 5, n0 = (i & 31) * 4;
        float4 v = ((const float4*)W)[i];
        uint32_t h0, l0, h1, l1;
        split2(v.x, v.y, h0, l0);
        split2(v.z, v.w, h1, l1);
        char* ph = smem + offH + k * W_PITCH + n0 * 2;
        char* pl = smem + offL + k * W_PITCH + n0 * 2;
        *(uint32_t*)ph = h0; *(uint32_t*)(ph + 4) = h1;
        *(uint32_t*)pl = l0; *(uint32_t*)(pl + 4) = l1;
    }
}

// one layer: acc[16][4] += A(regs) x W(smem hi/lo), 3-pass bf16
__device__ __forceinline__ void mma_layer(float acc[16][4],
                                          const uint32_t ahi[8][4], const uint32_t alo[8][4],
                                          uint32_t whiB, uint32_t wloB, int ks,
                                          int lr, int lc)
{
    for (int K = 0; K < ks; K++) {
        uint32_t ro = (uint32_t)((K * 16 + lr) * W_PITCH + lc * 2);
        #pragma unroll
        for (int c = 0; c < 8; c++) {
            uint32_t bh[4], bl[4];
            ldm4t(bh, whiB + ro + c * 32);
            ldm4t(bl, wloB + ro + c * 32);
            mma_bf16(acc[2 * c],     ahi[K], bh[0], bh[1]);
            mma_bf16(acc[2 * c + 1], ahi[K], bh[2], bh[3]);
            mma_bf16(acc[2 * c],     ahi[K], bl[0], bl[1]);
            mma_bf16(acc[2 * c + 1], ahi[K], bl[2], bl[3]);
            mma_bf16(acc[2 * c],     alo[K], bh[0], bh[1]);
            mma_bf16(acc[2 * c + 1], alo[K], bh[2], bh[3]);
        }
    }
}

// bias+relu on C frags -> next-layer A frags (hi/lo), and reset acc
__device__ __forceinline__ void epi_chain(float acc[16][4], const float* __restrict__ bias,
                                          uint32_t ahi[8][4], uint32_t alo[8][4], int ql)
{
    #pragma unroll
    for (int n = 0; n < 16; n++) {
        int c0 = n * 8 + ql * 2;
        float2 b = *(const float2*)(bias + c0);
        float v0 = fmaxf(acc[n][0] + b.x, 0.f);
        float v1 = fmaxf(acc[n][1] + b.y, 0.f);
        float v2 = fmaxf(acc[n][2] + b.x, 0.f);
        float v3 = fmaxf(acc[n][3] + b.y, 0.f);
        int K = n >> 1, h = (n & 1) * 2;
        split2(v0, v1, ahi[K][h],     alo[K][h]);
        split2(v2, v3, ahi[K][h + 1], alo[K][h + 1]);
        acc[n][0] = acc[n][1] = acc[n][2] = acc[n][3] = 0.f;
    }
}

__global__ __launch_bounds__(NTHR, 1) void mlp_kernel(
    const float* __restrict__ x,
    const float* __restrict__ emb_id, const float* __restrict__ emb_period,
    const float* __restrict__ emb_time,
    const float* __restrict__ Wf1, const float* __restrict__ bf1,
    const float* __restrict__ Wf2, const float* __restrict__ bf2,
    const float* __restrict__ Wc1, const float* __restrict__ bc1,
    const float* __restrict__ Wc2, const float* __restrict__ bc2,
    const float* __restrict__ Wb1, const float* __restrict__ bb1,
    const float* __restrict__ Wb2, const float* __restrict__ bb2)
{
    extern __shared__ char smem[];
    float* smf = (float*)smem;
    const int tid  = threadIdx.x;
    const int wid  = tid >> 5;
    const int lane = tid & 31;
    const int m0   = wid * 16;          // this warp's row base (within CTA)
    const int lr   = lane & 15;         // ldmatrix addr row part
    const int lc   = (lane >> 4) * 8;   // ldmatrix addr col part
    const int ql   = lane & 3;          // quad lane
    const int row0 = blockIdx.x * RPB;
    const uint32_t smb = (uint32_t)__cvta_generic_to_shared(smem);

    // ---- zero emb-A (hi/lo) + W buf0 (hi/lo): 7168 uint4 ----
    {
        uint4* z = (uint4*)smem;
        #pragma unroll
        for (int i = 0; i < 28; i++) z[tid + i * NTHR] = make_uint4(0, 0, 0, 0);
    }
    __syncthreads();

    // ---- prologue: emb fill, Wf1 stage, wc2bar/biases ----
    {
        int r = tid >> 1, h = tid & 1;
        int ip = (int)x[(row0 + r) * XCOLS + 0];
        int ii = (int)x[(row0 + r) * XCOLS + 1];
        int it = (int)x[(row0 + r) * XCOLS + 2];
        #pragma unroll
        for (int j = 0; j < 17; j++) {
            int c = h * 34 + 2 * j;
            float v[2];
            #pragma unroll
            for (int e = 0; e < 2; e++) {
                int cc = c + e;
                if      (cc < 8)  v[e] = emb_id    [ii * 8  + cc];
                else if (cc < 16) v[e] = emb_period[ip * 8  + (cc - 8)];
                else if (cc < 32) v[e] = emb_time  [it * 16 + (cc - 16)];
                else              v[e] = x[(row0 + r) * XCOLS + 3 + (cc - 32)];
            }
            uint32_t hi, lo; split2(v[0], v[1], hi, lo);
            *(uint32_t*)(smem + OFF_EA_HI + r * EA_PITCH + c * 2) = hi;
            *(uint32_t*)(smem + OFF_EA_LO + r * EA_PITCH + c * 2) = lo;
        }
    }
    stageW(Wf1, 68, smem, OFF_W0_HI, OFF_W0_LO, tid);
    if (tid < 128) {
        float s[6] = {0, 0, 0, 0, 0, 0};
        const float4* w4 = (const float4*)(Wc2 + tid * 48);
        #pragma unroll
        for (int v = 0; v < 12; v++) {
            float4 f = w4[v];
            s[(v * 4 + 0) % 6] += f.x; s[(v * 4 + 1) % 6] += f.y;
            s[(v * 4 + 2) % 6] += f.z; s[(v * 4 + 3) % 6] += f.w;
        }
        #pragma unroll
        for (int k = 0; k < 6; k++) smf[OFF_WC2 / 4 + tid * 8 + k] = s[k] * 0.125f;
        smf[OFF_BF1 / 4 + tid] = bf1[tid];
        smf[OFF_BF2 / 4 + tid] = bf2[tid];
        smf[OFF_BC1 / 4 + tid] = bc1[tid];
        smf[OFF_BB1 / 4 + tid] = bb1[tid];
        smf[OFF_WB2 / 4 + tid] = Wb2[tid];
    }
    if (tid < 6) {
        float s = 0.f;
        #pragma unroll
        for (int j = 0; j < 8; j++) s += bc2[j * 6 + tid];
        smf[OFF_BC2 / 4 + tid] = s * 0.125f;
    }
    if (tid == 6) smf[OFF_BC2 / 4 + 6] = bb2[0];
    __syncthreads();

    float acc[16][4];
    #pragma unroll
    for (int n = 0; n < 16; n++)
        acc[n][0] = acc[n][1] = acc[n][2] = acc[n][3] = 0.f;
    uint32_t ahi[8][4], alo[8][4];

    // ---- L1: A from emb smem via ldmatrix (5 ksteps), W0 = Wf1; stage Wf2 -> W1 ----
    stageW(Wf2, 128, smem, OFF_W1_HI, OFF_W1_LO, tid);
    {
        uint32_t eaH = smb + OFF_EA_HI + (m0 + lr) * EA_PITCH + lc * 2;
        uint32_t eaL = smb + OFF_EA_LO + (m0 + lr) * EA_PITCH + lc * 2;
        #pragma unroll
        for (int K = 0; K < 5; K++) {
            ldm4(ahi[K], eaH + K * 32);
            ldm4(alo[K], eaL + K * 32);
        }
    }
    mma_layer(acc, ahi, alo, smb + OFF_W0_HI, smb + OFF_W0_LO, 5, lr, lc);
    epi_chain(acc, smf + OFF_BF1 / 4, ahi, alo, ql);   // h1 -> regs
    __syncthreads();                                    // W1 staged; W0 free

    // ---- L2: W1 = Wf2; stage Wc1 -> W0 ----
    stageW(Wc1, 128, smem, OFF_W0_HI, OFF_W0_LO, tid);
    mma_layer(acc, ahi, alo, smb + OFF_W1_HI, smb + OFF_W1_LO, 8, lr, lc);
    epi_chain(acc, smf + OFF_BF2 / 4, ahi, alo, ql);   // h2 -> regs
    __syncthreads();                                    // W0 staged; W1 free

    // ---- L3: W0 = Wc1; stage Wb1 -> W1; epilogue = dot with wc2bar ----
    stageW(Wb1, 128, smem, OFF_W1_HI, OFF_W1_LO, tid);
    mma_layer(acc, ahi, alo, smb + OFF_W0_HI, smb + OFF_W0_LO, 8, lr, lc);
    {
        float a6r0[6] = {0, 0, 0, 0, 0, 0}, a6r1[6] = {0, 0, 0, 0, 0, 0};
        const float* bc1s = smf + OFF_BC1 / 4;
        const float* wc2s = smf + OFF_WC2 / 4;
        #pragma unroll
        for (int n = 0; n < 16; n++) {
            int c0 = n * 8 + ql * 2;
            float2 b = *(const float2*)(bc1s + c0);
            float v0 = fmaxf(acc[n][0] + b.x, 0.f);
            float v1 = fmaxf(acc[n][1] + b.y, 0.f);
            float v2 = fmaxf(acc[n][2] + b.x, 0.f);
            float v3 = fmaxf(acc[n][3] + b.y, 0.f);
            const float* w0 = wc2s + c0 * 8;
            const float* w1 = wc2s + (c0 + 1) * 8;
            #pragma unroll
            for (int k = 0; k < 6; k++) {
                a6r0[k] += v0 * w0[k] + v1 * w1[k];
                a6r1[k] += v2 * w0[k] + v3 * w1[k];
            }
            acc[n][0] = acc[n][1] = acc[n][2] = acc[n][3] = 0.f;
        }
        #pragma unroll
        for (int k = 0; k < 6; k++) {
            a6r0[k] += __shfl_xor_sync(0xffffffff, a6r0[k], 1);
            a6r0[k] += __shfl_xor_sync(0xffffffff, a6r0[k], 2);
            a6r1[k] += __shfl_xor_sync(0xffffffff, a6r1[k], 1);
            a6r1[k] += __shfl_xor_sync(0xffffffff, a6r1[k], 2);
        }
        if (ql == 0) {
            int row = m0 + (lane >> 2);
            #pragma unroll
            for (int k = 0; k < 6; k++) {
                smf[OFF_CBAR / 4 + row * 8 + k]       = a6r0[k] + smf[OFF_BC2 / 4 + k];
                smf[OFF_CBAR / 4 + (row + 8) * 8 + k] = a6r1[k] + smf[OFF_BC2 / 4 + k];
            }
        }
    }
    __syncthreads();                                    // W1 staged; W0 free

    // ---- L4: W1 = Wb1; epilogue = dot with Wb2 -> sbase ----
    mma_layer(acc, ahi, alo, smb + OFF_W1_HI, smb + OFF_W1_LO, 8, lr, lc);
    {
        float sb0 = 0.f, sb1 = 0.f;
        const float* bb1s = smf + OFF_BB1 / 4;
        const float* wb2s = smf + OFF_WB2 / 4;
        #pragma unroll
        for (int n = 0; n < 16; n++) {
            int c0 = n * 8 + ql * 2;
            float2 b = *(const float2*)(bb1s + c0);
            float2 w = *(const float2*)(wb2s + c0);
            sb0 += fmaxf(acc[n][0] + b.x, 0.f) * w.x + fmaxf(acc[n][1] + b.y, 0.f) * w.y;
            sb1 += fmaxf(acc[n][2] + b.x, 0.f) * w.x + fmaxf(acc[n][3] + b.y, 0.f) * w.y;
        }
        sb0 += __shfl_xor_sync(0xffffffff, sb0, 1);
        sb0 += __shfl_xor_sync(0xffffffff, sb0, 2);
        sb1 += __shfl_xor_sync(0xffffffff, sb1, 1);
        sb1 += __shfl_xor_sync(0xffffffff, sb1, 2);
        if (ql == 0) {
            int row = m0 + (lane >> 2);
            smf[OFF_CBAR / 4 + row * 8 + 6]       = sb0 + smf[OFF_BC2 / 4 + 6];
            smf[OFF_CBAR / 4 + (row + 8) * 8 + 6] = sb1 + smf[OFF_BC2 / 4 + 6];
        }
    }
    __syncthreads();

    // ---- per-row piecewise cubic coeffs + sbase -> g_scratch ----
    for (int task = tid; task < 384; task += NTHR) {
        int rb = task / 3, m = task - rb * 3;
        const float* c = smf + OFF_CBAR / 4 + rb * 8 + m;
        float c0 = c[0], c1 = c[1], c2 = c[2], c3 = c[3];
        const float k6 = 1.f / 6.f;
        float A0 = (c0 + 4.f * c1 + c2) * k6;
        float A1 = (c2 - c0) * 0.5f;
        float A2 = (c0 - 2.f * c1 + c2) * 0.5f;
        float A3 = (c3 - c0 + 3.f * (c1 - c2)) * k6;
        float d  = 1.5f - (float)m;           // u = 1.5*X + d
        float B0 = A0 + d * (A1 + d * (A2 + d * A3));
        float B1 = 1.5f * (A1 + d * (2.f * A2 + 3.f * A3 * d));
        float B2 = 2.25f * (A2 + 3.f * A3 * d);
        float B3 = 3.375f * A3;
        ((float4*)g_scratch)[(row0 + rb) * 4 + m] = make_float4(B0, B1, B2, B3);
    }
    if (tid < 128)
        g_scratch[(row0 + tid) * 16 + 12] = smf[OFF_CBAR / 4 + tid * 8 + 6];
}

// ---------------- budget kernel: 1024 blocks x 256 thr, 1 float4/thread ----------------
__global__ __launch_bounds__(256, 8) void budget_kernel(
    const float* __restrict__ budget, float* __restrict__ out)
{
    __shared__ float cb[32];    // 2 rows x 16 coefs
    int tid = threadIdx.x;
    int b = blockIdx.x;
    if (tid < 8)
        ((float4*)cb)[tid] = ((const float4*)(g_scratch + b * 2 * 16))[tid];
    __syncthreads();

    int q = b * 256 + tid;
    int rl = tid >> 7;                 // row within block (0/1)
    float4 bv = ((const float4*)budget)[q];
    float sb = cb[rl * 16 + 12];
    const float4* cb4 = (const float4*)(cb + rl * 16);
    float xs[4] = {bv.x, bv.y, bv.z, bv.w};
    float o[4];
    #pragma unroll
    for (int e = 0; e < 4; e++) {
        float X = xs[e];
        float tp = fmaf(X, 1.5f, 1.5f);
        int m = min((int)tp, 2);
        float4 B = cb4[m];
        float sp = fmaf(fmaf(fmaf(B.w, X, B.z), X, B.y), X, B.x);
        float u = X * X;
        float P = fmaf(u, fmaf(u, fmaf(u, fmaf(u, 2.1357286e-5f, -2.1081349e-4f),
                                       2.0833333e-3f), -2.0833333e-2f), 0.25f);
        float sil = X * fmaf(X, P, 0.5f);
        o[e] = sb * (sil + sp);
    }
    ((float4*)out)[q] = make_float4(o[0], o[1], o[2], o[3]);
}

extern "C" void kernel_launch(void* const* d_in, const int* in_sizes, int n_in,
                              void* d_out, int out_size)
{
    const float* x          = (const float*)d_in[0];
    const float* budget     = (const float*)d_in[1];
    const float* emb_id     = (const float*)d_in[2];
    const float* emb_period = (const float*)d_in[3];
    const float* emb_time   = (const float*)d_in[4];
    const float* Wf1 = (const float*)d_in[5];
    const float* bf1 = (const float*)d_in[6];
    const float* Wf2 = (const float*)d_in[7];
    const float* bf2 = (const float*)d_in[8];
    const float* Wc1 = (const float*)d_in[9];
    const float* bc1 = (const float*)d_in[10];
    const float* Wc2 = (const float*)d_in[11];
    const float* bc2 = (const float*)d_in[12];
    // d_in[13..16] = Ws1/bs1/Ws2/bs2 : unused in reference output
    const float* Wb1 = (const float*)d_in[17];
    const float* bb1 = (const float*)d_in[18];
    const float* Wb2 = (const float*)d_in[19];
    const float* bb2 = (const float*)d_in[20];

    cudaFuncSetAttribute(mlp_kernel, cudaFuncAttributeMaxDynamicSharedMemorySize, MLP_SMEM);

    mlp_kernel<<<NCTA, NTHR, MLP_SMEM>>>(
        x, emb_id, emb_period, emb_time,
        Wf1, bf1, Wf2, bf2, Wc1, bc1, Wc2, bc2,
        Wb1, bb1, Wb2, bb2);
    budget_kernel<<<1024, 256>>>(budget, (float*)d_out);
}

// round 8
// speedup vs baseline: 2.0148x; 2.0148x over previous
#include <cuda_runtime.h>
#include <cuda_bf16.h>
#include <cstdint>

#define BATCH 2048
#define RPB   16       // rows per MLP CTA
#define NCTA  128
#define NTHR  256
#define XCOLS 39
#define HID   128
#define WP    272      // W/A smem pitch bytes (136 bf16)

// ---- smem byte offsets ----
#define S0H 0
#define S0L 34816
#define S1H 69632
#define S1L 104448
#define E_H 139264     // emb A hi [16][WP]
#define E_L 143616
#define AAH 147968     // actA
#define AAL 152320
#define ABH 156672     // actB
#define ABL 161024
#define OHC 165376     // hc f32 [16][128]
#define OHB 173568     // hb f32 [16][128]
#define OW2 181760     // wc2bar [128][8] f32
#define OB1 185856     // bf1 [128]
#define OB2 186368     // bf2
#define OB3 186880     // bc1
#define OB4 187392     // bb1
#define OWB 187904     // Wb2
#define OBC 188416     // bc2bar[6], [6]=bb2
#define OCB 188448     // cbar [16][8]
#define OCF 188960     // coefB [16][4][4]
#define MLP_SMEM 189984

// preconverted weights: [m][128][128] bf16, m = {f1(rows>=68 zero), f2, c1, b1}
__device__ __nv_bfloat16 g_whi[4 * 128 * 128];
__device__ __nv_bfloat16 g_wlo[4 * 128 * 128];
__device__ float g_wc2bar[128 * 8];

// ---------------- PTX wrappers (verified R7) ----------------
__device__ __forceinline__ void ldm4(uint32_t r[4], uint32_t a) {
    asm volatile("ldmatrix.sync.aligned.m8n8.x4.shared.b16 {%0,%1,%2,%3}, [%4];"
                 : "=r"(r[0]), "=r"(r[1]), "=r"(r[2]), "=r"(r[3]) : "r"(a));
}
__device__ __forceinline__ void ldm4t(uint32_t r[4], uint32_t a) {
    asm volatile("ldmatrix.sync.aligned.m8n8.x4.trans.shared.b16 {%0,%1,%2,%3}, [%4];"
                 : "=r"(r[0]), "=r"(r[1]), "=r"(r[2]), "=r"(r[3]) : "r"(a));
}
__device__ __forceinline__ void mma_bf16(float d[4], const uint32_t a[4],
                                         uint32_t b0, uint32_t b1) {
    asm("mma.sync.aligned.m16n8k16.row.col.f32.bf16.bf16.f32 "
        "{%0,%1,%2,%3}, {%4,%5,%6,%7}, {%8,%9}, {%0,%1,%2,%3};"
        : "+f"(d[0]), "+f"(d[1]), "+f"(d[2]), "+f"(d[3])
        : "r"(a[0]), "r"(a[1]), "r"(a[2]), "r"(a[3]), "r"(b0), "r"(b1));
}
__device__ __forceinline__ void split2(float v0, float v1, uint32_t& hi, uint32_t& lo) {
    __nv_bfloat162 h = __floats2bfloat162_rn(v0, v1);
    float f0 = __bfloat162float(h.x), f1 = __bfloat162float(h.y);
    __nv_bfloat162 g = __floats2bfloat162_rn(v0 - f0, v1 - f1);
    hi = *reinterpret_cast<uint32_t*>(&h);
    lo = *reinterpret_cast<uint32_t*>(&g);
}
__device__ __forceinline__ void cp16(uint32_t dst_smem, const void* src) {
    asm volatile("cp.async.cg.shared.global [%0], [%1], 16;\n" :: "r"(dst_smem), "l"(src));
}
#define CP_COMMIT() asm volatile("cp.async.commit_group;\n" ::: "memory")
#define CP_WAIT0()  asm volatile("cp.async.wait_group 0;\n" ::: "memory")
#define CP_WAIT1()  asm volatile("cp.async.wait_group 1;\n" ::: "memory")

// ---------------- weight preconvert kernel ----------------
__global__ __launch_bounds__(256) void convert_kernel(
    const float* __restrict__ Wf1, const float* __restrict__ Wf2,
    const float* __restrict__ Wc1, const float* __restrict__ Wb1,
    const float* __restrict__ Wc2)
{
    int tid = threadIdx.x;
    if (blockIdx.x < 64) {
        int idx = blockIdx.x * 256 + tid;      // 16384 float4 tasks
        int m = idx >> 12, r = idx & 4095;
        int k = r >> 5, n4 = (r & 31) * 4;
        float4 v = make_float4(0.f, 0.f, 0.f, 0.f);
        const float* src = (m == 0) ? Wf1 : (m == 1) ? Wf2 : (m == 2) ? Wc1 : Wb1;
        if (m != 0 || k < 68) v = *(const float4*)(src + k * 128 + n4);
        uint32_t h0, l0, h1, l1;
        split2(v.x, v.y, h0, l0);
        split2(v.z, v.w, h1, l1);
        int e = (m << 14) + k * 128 + n4;
        *(uint2*)((char*)g_whi + e * 2) = make_uint2(h0, h1);
        *(uint2*)((char*)g_wlo + e * 2) = make_uint2(l0, l1);
    } else if (tid < 128) {
        float s[6] = {0, 0, 0, 0, 0, 0};
        const float4* w4 = (const float4*)(Wc2 + tid * 48);
        #pragma unroll
        for (int v = 0; v < 12; v++) {
            float4 f = w4[v];
            s[(v * 4 + 0) % 6] += f.x; s[(v * 4 + 1) % 6] += f.y;
            s[(v * 4 + 2) % 6] += f.z; s[(v * 4 + 3) % 6] += f.w;
        }
        #pragma unroll
        for (int k = 0; k < 6; k++) g_wc2bar[tid * 8 + k] = s[k] * 0.125f;
        g_wc2bar[tid * 8 + 6] = 0.f; g_wc2bar[tid * 8 + 7] = 0.f;
    }
}

// stage preconverted matrix m into smem hi/lo tiles [rows][WP]
__device__ __forceinline__ void stage_pre(int m, char* smem, int offH, int offL,
                                          int rows, int tid)
{
    const char* sH = (const char*)(g_whi + (m << 14));
    const char* sL = (const char*)(g_wlo + (m << 14));
    uint32_t dH = (uint32_t)__cvta_generic_to_shared(smem + offH);
    uint32_t dL = (uint32_t)__cvta_generic_to_shared(smem + offL);
    int tot = rows * 16;
    for (int i = tid; i < tot; i += NTHR) {
        int k = i >> 4, n = (i & 15) * 16;
        cp16(dH + k * WP + n, sH + k * 256 + n);
        cp16(dL + k * WP + n, sL + k * 256 + n);
    }
}

// load A fragments (ks ksteps) from act buffer
__device__ __forceinline__ void loadA(uint32_t ahi[8][4], uint32_t alo[8][4],
                                      uint32_t bH, uint32_t bL, int ks, int lr, int lc)
{
    uint32_t base = lr * WP + lc * 2;
    for (int K = 0; K < ks; K++) {
        ldm4(ahi[K], bH + base + K * 32);
        ldm4(alo[K], bL + base + K * 32);
    }
}

// warp MMA over its 16-col N slice, 3-pass bf16
__device__ __forceinline__ void mma16(float acc[2][4],
                                      const uint32_t ahi[8][4], const uint32_t alo[8][4],
                                      uint32_t wH, uint32_t wL, int ks,
                                      int lr, uint32_t wcolb)
{
    for (int K = 0; K < ks; K++) {
        uint32_t ro = (uint32_t)((K * 16 + lr) * WP) + wcolb;
        uint32_t bh[4], bl[4];
        ldm4t(bh, wH + ro);
        ldm4t(bl, wL + ro);
        mma_bf16(acc[0], ahi[K], bh[0], bh[1]);
        mma_bf16(acc[1], ahi[K], bh[2], bh[3]);
        mma_bf16(acc[0], ahi[K], bl[0], bl[1]);
        mma_bf16(acc[1], ahi[K], bl[2], bl[3]);
        mma_bf16(acc[0], alo[K], bh[0], bh[1]);
        mma_bf16(acc[1], alo[K], bh[2], bh[3]);
    }
}

// bias+relu -> bf16 hi/lo act buffer; reset acc
__device__ __forceinline__ void epi_act(float acc[2][4], const float* __restrict__ bias,
                                        char* smem, int offH, int offL,
                                        int w, int lane)
{
    int r0 = lane >> 2, ql = lane & 3;
    #pragma unroll
    for (int t = 0; t < 2; t++) {
        int c = w * 16 + t * 8 + 2 * ql;
        float2 b = *(const float2*)(bias + c);
        float v0 = fmaxf(acc[t][0] + b.x, 0.f);
        float v1 = fmaxf(acc[t][1] + b.y, 0.f);
        float v2 = fmaxf(acc[t][2] + b.x, 0.f);
        float v3 = fmaxf(acc[t][3] + b.y, 0.f);
        uint32_t h0, l0, h1, l1;
        split2(v0, v1, h0, l0);
        split2(v2, v3, h1, l1);
        *(uint32_t*)(smem + offH + r0 * WP + c * 2)       = h0;
        *(uint32_t*)(smem + offL + r0 * WP + c * 2)       = l0;
        *(uint32_t*)(smem + offH + (r0 + 8) * WP + c * 2) = h1;
        *(uint32_t*)(smem + offL + (r0 + 8) * WP + c * 2) = l1;
        acc[t][0] = acc[t][1] = acc[t][2] = acc[t][3] = 0.f;
    }
}

// bias+relu -> f32 buffer [16][128]; reset acc
__device__ __forceinline__ void epi_f32(float acc[2][4], const float* __restrict__ bias,
                                        float* __restrict__ dst, int w, int lane)
{
    int r0 = lane >> 2, ql = lane & 3;
    #pragma unroll
    for (int t = 0; t < 2; t++) {
        int c = w * 16 + t * 8 + 2 * ql;
        float2 b = *(const float2*)(bias + c);
        *(float2*)(dst + r0 * 128 + c)       = make_float2(fmaxf(acc[t][0] + b.x, 0.f),
                                                           fmaxf(acc[t][1] + b.y, 0.f));
        *(float2*)(dst + (r0 + 8) * 128 + c) = make_float2(fmaxf(acc[t][2] + b.x, 0.f),
                                                           fmaxf(acc[t][3] + b.y, 0.f));
        acc[t][0] = acc[t][1] = acc[t][2] = acc[t][3] = 0.f;
    }
}

__global__ __launch_bounds__(NTHR, 1) void mlp_kernel(
    const float* __restrict__ x,
    const float* __restrict__ budget,
    const float* __restrict__ emb_id, const float* __restrict__ emb_period,
    const float* __restrict__ emb_time,
    const float* __restrict__ bf1, const float* __restrict__ bf2,
    const float* __restrict__ bc1, const float* __restrict__ bc2,
    const float* __restrict__ bb1, const float* __restrict__ Wb2,
    const float* __restrict__ bb2,
    float* __restrict__ out)
{
    extern __shared__ char smem[];
    float* smf = (float*)smem;
    const int tid  = threadIdx.x;
    const int w    = tid >> 5;
    const int lane = tid & 31;
    const int lr   = lane & 15;
    const int lc   = (lane >> 4) * 8;
    const int row0 = blockIdx.x * RPB;
    const uint32_t smb = (uint32_t)__cvta_generic_to_shared(smem);
    const uint32_t wcolb = (uint32_t)(w * 16 + lc) * 2;

    // zero E hi/lo (covers zero-pad cols 68..79); 544 uint4
    for (int i = tid; i < 544; i += NTHR)
        ((uint4*)(smem + E_H))[i] = make_uint4(0, 0, 0, 0);

    // stage f1 (80 rows incl. zero rows) -> S0, f2 -> S1
    stage_pre(0, smem, S0H, S0L, 80, tid);  CP_COMMIT();
    stage_pre(1, smem, S1H, S1L, 128, tid); CP_COMMIT();

    // wc2bar copy, biases
    ((float4*)(smem + OW2))[tid] = ((const float4*)g_wc2bar)[tid];
    if (tid < 128) {
        smf[OB1 / 4 + tid] = bf1[tid];
        smf[OB2 / 4 + tid] = bf2[tid];
        smf[OB3 / 4 + tid] = bc1[tid];
        smf[OB4 / 4 + tid] = bb1[tid];
        smf[OWB / 4 + tid] = Wb2[tid];
    }
    if (tid < 6) {
        float s = 0.f;
        #pragma unroll
        for (int j = 0; j < 8; j++) s += bc2[j * 6 + tid];
        smf[OBC / 4 + tid] = s * 0.125f;
    }
    if (tid == 6) smf[OBC / 4 + 6] = bb2[0];
    __syncthreads();   // E zeros visible before emb fill

    // emb fill: 16 rows x 68 cols, bf16 hi/lo
    for (int idx = tid; idx < RPB * 68; idx += NTHR) {
        int r = idx / 68, c = idx % 68;
        float v;
        if (c < 8) {
            v = emb_id[(int)x[(row0 + r) * XCOLS + 1] * 8 + c];
        } else if (c < 16) {
            v = emb_period[(int)x[(row0 + r) * XCOLS + 0] * 8 + (c - 8)];
        } else if (c < 32) {
            v = emb_time[(int)x[(row0 + r) * XCOLS + 2] * 16 + (c - 16)];
        } else {
            v = x[(row0 + r) * XCOLS + 3 + (c - 32)];
        }
        __nv_bfloat16 h = __float2bfloat16(v);
        __nv_bfloat16 l = __float2bfloat16(v - __bfloat162float(h));
        *(__nv_bfloat16*)(smem + E_H + r * WP + c * 2) = h;
        *(__nv_bfloat16*)(smem + E_L + r * WP + c * 2) = l;
    }
    CP_WAIT1();        // f1 arrived
    __syncthreads();   // emb visible

    float acc[2][4];
    acc[0][0] = acc[0][1] = acc[0][2] = acc[0][3] = 0.f;
    acc[1][0] = acc[1][1] = acc[1][2] = acc[1][3] = 0.f;
    uint32_t ahi[8][4], alo[8][4];

    // ---- L1: E x Wf1(S0) -> actA ----
    loadA(ahi, alo, smb + E_H, smb + E_L, 5, lr, lc);
    mma16(acc, ahi, alo, smb + S0H, smb + S0L, 5, lr, wcolb);
    epi_act(acc, smf + OB1 / 4, smem, AAH, AAL, w, lane);
    CP_WAIT0();        // f2 arrived
    __syncthreads();   // actA visible, S0 free

    // ---- L2: actA x Wf2(S1) -> actB;  prefetch c1 -> S0 ----
    stage_pre(2, smem, S0H, S0L, 128, tid); CP_COMMIT();
    loadA(ahi, alo, smb + AAH, smb + AAL, 8, lr, lc);
    mma16(acc, ahi, alo, smb + S1H, smb + S1L, 8, lr, wcolb);
    epi_act(acc, smf + OB2 / 4, smem, ABH, ABL, w, lane);
    __syncthreads();   // actB visible, S1 free

    // ---- prefetch b1 -> S1; L3: actB x Wc1(S0) -> hc ----
    stage_pre(3, smem, S1H, S1L, 128, tid); CP_COMMIT();
    CP_WAIT1();        // c1 arrived
    loadA(ahi, alo, smb + ABH, smb + ABL, 8, lr, lc);
    mma16(acc, ahi, alo, smb + S0H, smb + S0L, 8, lr, wcolb);
    epi_f32(acc, smf + OB3 / 4, smf + OHC / 4, w, lane);

    // ---- L4: actB x Wb1(S1) -> hb (same A frags) ----
    CP_WAIT0();        // b1 arrived
    mma16(acc, ahi, alo, smb + S1H, smb + S1L, 8, lr, wcolb);
    epi_f32(acc, smf + OB4 / 4, smf + OHB / 4, w, lane);
    __syncthreads();

    // ---- final dots: cbar[16][6], sbase ----
    {
        int rb = tid >> 4, slot = tid & 15;
        if (slot < 6) {
            const float* hc = smf + OHC / 4 + rb * 128;
            float s = 0.f;
            for (int i = 0; i < HID; i++) s += hc[i] * smf[OW2 / 4 + i * 8 + slot];
            smf[OCB / 4 + rb * 8 + slot] = s + smf[OBC / 4 + slot];
        } else if (slot == 6) {
            const float* hb = smf + OHB / 4 + rb * 128;
            float s = 0.f;
            for (int i = 0; i < HID; i++) s += hb[i] * smf[OWB / 4 + i];
            smf[OCB / 4 + rb * 8 + 6] = s + smf[OBC / 4 + 6];
        }
    }
    __syncthreads();

    // ---- per-row piecewise cubic in X ----
    if (tid < 48) {
        int rb = tid / 3, m = tid - rb * 3;
        const float* c = smf + OCB / 4 + rb * 8 + m;
        float c0 = c[0], c1 = c[1], c2 = c[2], c3 = c[3];
        const float k6 = 1.f / 6.f;
        float A0 = (c0 + 4.f * c1 + c2) * k6;
        float A1 = (c2 - c0) * 0.5f;
        float A2 = (c0 - 2.f * c1 + c2) * 0.5f;
        float A3 = (c3 - c0 + 3.f * (c1 - c2)) * k6;
        float d  = 1.5f - (float)m;
        float B0 = A0 + d * (A1 + d * (A2 + d * A3));
        float B1 = 1.5f * (A1 + d * (2.f * A2 + 3.f * A3 * d));
        float B2 = 2.25f * (A2 + 3.f * A3 * d);
        float B3 = 3.375f * A3;
        ((float4*)(smem + OCF))[rb * 4 + m] = make_float4(B0, B1, B2, B3);
    }
    __syncthreads();

    // ---- budget phase: 16 rows x 512 points = 2048 float4 ----
    const float4* bud4 = (const float4*)budget + row0 * 128;
    float4* out4 = (float4*)out + row0 * 128;
    const float4* cb4 = (const float4*)(smem + OCF);
    #pragma unroll
    for (int it = 0; it < 8; it++) {
        int q = tid + it * NTHR;
        int row = q >> 7;
        float4 bv = bud4[q];
        float sb = smf[OCB / 4 + row * 8 + 6];
        float xs[4] = {bv.x, bv.y, bv.z, bv.w};
        float o[4];
        #pragma unroll
        for (int e = 0; e < 4; e++) {
            float X = xs[e];
            float tp = fmaf(X, 1.5f, 1.5f);
            int m = min((int)tp, 2);
            float4 B = cb4[row * 4 + m];
            float sp = fmaf(fmaf(fmaf(B.w, X, B.z), X, B.y), X, B.x);
            float u = X * X;
            float P = fmaf(u, fmaf(u, fmaf(u, fmaf(u, 2.1357286e-5f, -2.1081349e-4f),
                                           2.0833333e-3f), -2.0833333e-2f), 0.25f);
            float sil = X * fmaf(X, P, 0.5f);
            o[e] = sb * (sil + sp);
        }
        out4[q] = make_float4(o[0], o[1], o[2], o[3]);
    }
}

extern "C" void kernel_launch(void* const* d_in, const int* in_sizes, int n_in,
                              void* d_out, int out_size)
{
    const float* x          = (const float*)d_in[0];
    const float* budget     = (const float*)d_in[1];
    const float* emb_id     = (const float*)d_in[2];
    const float* emb_period = (const float*)d_in[3];
    const float* emb_time   = (const float*)d_in[4];
    const float* Wf1 = (const float*)d_in[5];
    const float* bf1 = (const float*)d_in[6];
    const float* Wf2 = (const float*)d_in[7];
    const float* bf2 = (const float*)d_in[8];
    const float* Wc1 = (const float*)d_in[9];
    const float* bc1 = (const float*)d_in[10];
    const float* Wc2 = (const float*)d_in[11];
    const float* bc2 = (const float*)d_in[12];
    // d_in[13..16] = Ws1/bs1/Ws2/bs2 : unused in reference output
    const float* Wb1 = (const float*)d_in[17];
    const float* bb1 = (const float*)d_in[18];
    const float* Wb2 = (const float*)d_in[19];
    const float* bb2 = (const float*)d_in[20];

    cudaFuncSetAttribute(mlp_kernel, cudaFuncAttributeMaxDynamicSharedMemorySize, MLP_SMEM);

    convert_kernel<<<65, 256>>>(Wf1, Wf2, Wc1, Wb1, Wc2);
    mlp_kernel<<<NCTA, NTHR, MLP_SMEM>>>(
        x, budget, emb_id, emb_period, emb_time,
        bf1, bf2, bc1, bc2, bb1, Wb2, bb2, (float*)d_out);
}